// round 17
// baseline (speedup 1.0000x reference)
#include <cuda_runtime.h>

// ---------------------------------------------------------------------------
// LLG micromagnetics RK4 solver — halo-4 tiled persistent kernel.
// 480 threads x 2 slots (region 24x40 = 960 cells), float4 AoS shared memory
// (LDS.128 neighbor fetches), one 8-neighbor flag handshake per step.
//
// 256x256 grid. 128 blocks (16x8 block grid), each owns a 16x32 tile and
// processes a 24x40 region (halo 4 = one RK4 step's dependency radius).
// All 4 RK4 substages run block-locally in shared memory (shrinking pads
// 1..4). Inter-block sync: st.release.gpu / ld.acquire.gpu flags, with
// double-buffered global m.
// ---------------------------------------------------------------------------

namespace {
constexpr int NXC   = 256;
constexpr int NYC   = 256;
constexpr int NCELL = NXC * NYC;

constexpr int BGR  = 16;
constexpr int BGC  = 8;
constexpr int NBLK = BGR * BGC;      // 128
constexpr int TR   = 16;
constexpr int TC   = 32;
constexpr int HALO = 4;
constexpr int RH   = TR + 2 * HALO;  // 24
constexpr int RW   = TC + 2 * HALO;  // 40
constexpr int RCELLS = RH * RW;      // 960
constexpr int NTHR  = 480;           // 2 region cells per thread
constexpr int SLOTS = 2;

constexpr int TSTEPS = 256;
constexpr int NSRC   = 3;
constexpr int NPROBE = 5;
constexpr int NSIG   = 2;
constexpr int RELAX  = 100;
constexpr int TOTSTEPS = RELAX + NSIG * TSTEPS;  // 612

constexpr double GAMMA_LL = 175950000000.0;
constexpr double DT       = 5e-12;
constexpr double A_EXCH   = 3.5e-12;
constexpr double DX       = 5e-08;
constexpr double MU0      = 1.2566370614359172e-06;
constexpr float  CSOT     = 1e-4f;
constexpr float  HSTEP    = (float)(GAMMA_LL * DT);   // 0.87975
}

__device__ float4   g_m[2][NCELL];        // ping-pong field buffers (AoS)
__device__ float4   g_mrel[NCELL];        // m_relaxed snapshot
__device__ unsigned g_flags[NBLK];        // per-block step counters
__device__ int      g_zero_int = 0;

// ---------------------------------------------------------------------------
// One torque eval; stage field in float4 AoS smem (one LDS.128 per neighbor).
// ---------------------------------------------------------------------------
__device__ __forceinline__ void evalk4(
    const float4* __restrict__ S,
    int u, int d, int l, int r,
    float sx, float sy, float sz,
    float bxv, float byv, float bzvv,
    float cex, float dzf, float negInv, float alpha,
    float& kx, float& ky, float& kz)
{
    float4 U = S[u], D4 = S[d], L4 = S[l], R4 = S[r];

    float lx = U.x + D4.x + L4.x + R4.x - 4.0f * sx;
    float ly = U.y + D4.y + L4.y + R4.y - 4.0f * sy;
    float lz = U.z + D4.z + L4.z + R4.z - 4.0f * sz;

    float Bx = fmaf(cex, lx, bxv);
    float By = fmaf(cex, ly, byv);
    float Bz = fmaf(dzf, sz, fmaf(cex, lz, bzvv));

    float c1x = sy * Bz - sz * By;
    float c1y = sz * Bx - sx * Bz;
    float c1z = sx * By - sy * Bx;
    float c2x = sy * c1z - sz * c1y;
    float c2y = sz * c1x - sx * c1z;
    float c2z = sx * c1y - sy * c1x;

    kx = fmaf(negInv, fmaf(alpha, c2x, c1x),  CSOT * (sx * sy));
    ky = fmaf(negInv, fmaf(alpha, c2y, c1y), -CSOT * fmaf(sx, sx, sz * sz));
    kz = fmaf(negInv, fmaf(alpha, c2z, c1z),  CSOT * (sy * sz));
}

// ---------------------------------------------------------------------------
__global__ void init_flags_kernel() {
    if (threadIdx.x < NBLK) g_flags[threadIdx.x] = 0u;
}

// Mid stage: eval from PB, accumulate W*k, write m+COEF*k into QB and carry
// in sv registers.
#define STAGE(PAD, PB, QB, COEF, W)                                          \
    _Pragma("unroll")                                                        \
    for (int j = 0; j < SLOTS; ++j) {                                        \
        if (mpad[j] >= (PAD)) {                                              \
            float kx, ky, kz;                                                \
            evalk4(QB##_dummy_##PB, uN[j], dN[j], lN[j], rN[j],              \
                  svx[j], svy[j], svz[j], bxv[j], byv[j], bzv[j],            \
                  cex, dzf, negInv, alpha, kx, ky, kz);                      \
        }                                                                    \
    }

__global__ void __launch_bounds__(NTHR, 1) mm_solver_kernel(
    const float* __restrict__ sig,        // (NSIG, TSTEPS, NSRC) flat
    const float* __restrict__ Bext,       // (1, 3, NXC, NYC)
    const float* __restrict__ Msat_p,
    const int*   __restrict__ src_pos,    // (NSRC, 2)
    const int*   __restrict__ probe_pos,  // (NPROBE, 2)
    const int*   __restrict__ fb_p,
    float*       __restrict__ out)        // (NSIG, TSTEPS, NPROBE) flat
{
    __shared__ float4 s_m[RCELLS];
    __shared__ float4 s_a[RCELLS];
    __shared__ float4 s_b[RCELLS];

    const int tid = threadIdx.x;
    const int bid = blockIdx.x;
    const int br = bid >> 3, bc = bid & 7;
    const int org_r = br * TR - HALO;
    const int org_c = bc * TC - HALO;

    // polling threads 0..7 each own one neighbor block
    int nbid = -1;
    if (tid < 8) {
        const int dr8[8] = {-1,-1,-1, 0, 0, 1, 1, 1};
        const int dc8[8] = {-1, 0, 1,-1, 1,-1, 0, 1};
        int nr = br + dr8[tid], ncb = bc + dc8[tid];
        if (nr >= 0 && nr < BGR && ncb >= 0 && ncb < BGC)
            nbid = nr * BGC + ncb;
    }

    const float Msat = *Msat_p;
    const float cex  = (float)(2.0 * A_EXCH) / (Msat * (float)DX * (float)DX);
    const float dzf  = -(float)MU0 * Msat;
    const int   fb   = *fb_p;

    // ---- per-slot loop-invariant precompute ----
    int   uN[SLOTS], dN[SLOTS], lN[SLOTS], rN[SLOTS], gld[SLOTS];
    int   mpad[SLOTS], sid[SLOTS], pid[SLOTS];
    float bxv[SLOTS], byv[SLOTS], bz0[SLOTS];

    #pragma unroll
    for (int j = 0; j < SLOTS; ++j) {
        int idx = tid + j * NTHR;                 // 0..959
        int lr = idx / RW, lc = idx - lr * RW;
        int gr = org_r + lr, gc = org_c + lc;
        int cr = min(max(gr, 0), NXC - 1);
        int cc = min(max(gc, 0), NYC - 1);
        int ur  = max(cr - 1, 0),  dw  = min(cr + 1, NXC - 1);
        int lcl = max(cc - 1, 0),  rcl = min(cc + 1, NYC - 1);

        uN[j]  = (ur - org_r) * RW + (cc  - org_c);
        dN[j]  = (dw - org_r) * RW + (cc  - org_c);
        lN[j]  = (cr - org_r) * RW + (lcl - org_c);
        rN[j]  = (cr - org_r) * RW + (rcl - org_c);
        gld[j] = cr * NYC + cc;

        bxv[j] = Bext[0 * NCELL + gld[j]];
        byv[j] = Bext[1 * NCELL + gld[j]];
        bz0[j] = Bext[2 * NCELL + gld[j]];

        mpad[j] = min(min(lr, RH - 1 - lr), min(lc, RW - 1 - lc));

        sid[j] = -1;
        #pragma unroll
        for (int k = 0; k < NSRC; k++)
            if (src_pos[2 * k] == cr && src_pos[2 * k + 1] == cc) sid[j] = k;
        pid[j] = -1;
        #pragma unroll
        for (int k = 0; k < NPROBE; k++)
            if (probe_pos[2 * k] == cr && probe_pos[2 * k + 1] == cc) pid[j] = k;
    }

    const float H  = HSTEP;
    const float H2 = 0.5f * HSTEP;
    const float H6 = HSTEP / 6.0f;

    float mx[SLOTS],  my[SLOTS],  mz[SLOTS];
    float svx[SLOTS], svy[SLOTS], svz[SLOTS];
    float ax[SLOTS],  ay[SLOTS],  az[SLOTS];
    float bzv[SLOTS];
    float pz0[SLOTS] = {0.0f, 0.0f};

    for (int t = 0; t < TOTSTEPS; ++t) {
        const bool  driven = (t >= RELAX);
        const float alpha  = driven ? 0.01f : 0.5f;
        const float negInv = -1.0f / (1.0f + alpha * alpha);
        const int   rp     = t & 1;

        // ---- wait: 8 neighbors finished step t-1 (double-buffered m) ----
        if (t > 0) {
            if (nbid >= 0) {
                unsigned v;
                while (true) {
                    asm volatile("ld.acquire.gpu.b32 %0, [%1];"
                                 : "=r"(v) : "l"(&g_flags[nbid]) : "memory");
                    if ((int)v >= t) break;
                    __nanosleep(20);
                }
            }
            __syncthreads();
        }

        // ---- load region m into registers + s_m (LDG.128 / STS.128) ----
        #pragma unroll
        for (int j = 0; j < SLOTS; ++j) {
            int idx = tid + j * NTHR;
            float4 v;
            if (t == 0) {
                v = make_float4(0.0f, 1.0f, 0.0f, 0.0f);   // m0 = (0,1,0)
            } else if (t == RELAX + TSTEPS) {              // signal-1 reset
                v = __ldcg(&g_mrel[gld[j]]);
            } else {
                v = __ldcg(&g_m[rp][gld[j]]);
            }
            mx[j] = v.x; my[j] = v.y; mz[j] = v.z;
            svx[j] = v.x; svy[j] = v.y; svz[j] = v.z;
            s_m[idx] = v;

            bzv[j] = bz0[j];
            if (driven && sid[j] >= 0)
                bzv[j] += __ldg(&sig[(t - RELAX) * NSRC + sid[j]]);
        }
        __syncthreads();

        float kx, ky, kz;

        // ---- stage 1: k1 from s_m -> s_a (pad >= 1) ----
        #pragma unroll
        for (int j = 0; j < SLOTS; ++j) {
            if (mpad[j] >= 1) {
                evalk4(s_m, uN[j], dN[j], lN[j], rN[j],
                       svx[j], svy[j], svz[j], bxv[j], byv[j], bzv[j],
                       cex, dzf, negInv, alpha, kx, ky, kz);
                ax[j] = kx; ay[j] = ky; az[j] = kz;
                svx[j] = fmaf(H2, kx, mx[j]);
                svy[j] = fmaf(H2, ky, my[j]);
                svz[j] = fmaf(H2, kz, mz[j]);
                s_a[tid + j * NTHR] = make_float4(svx[j], svy[j], svz[j], 0.0f);
            }
        }
        __syncthreads();

        // ---- stage 2: k2 from s_a -> s_b (pad >= 2) ----
        #pragma unroll
        for (int j = 0; j < SLOTS; ++j) {
            if (mpad[j] >= 2) {
                evalk4(s_a, uN[j], dN[j], lN[j], rN[j],
                       svx[j], svy[j], svz[j], bxv[j], byv[j], bzv[j],
                       cex, dzf, negInv, alpha, kx, ky, kz);
                ax[j] = fmaf(2.0f, kx, ax[j]);
                ay[j] = fmaf(2.0f, ky, ay[j]);
                az[j] = fmaf(2.0f, kz, az[j]);
                svx[j] = fmaf(H2, kx, mx[j]);
                svy[j] = fmaf(H2, ky, my[j]);
                svz[j] = fmaf(H2, kz, mz[j]);
                s_b[tid + j * NTHR] = make_float4(svx[j], svy[j], svz[j], 0.0f);
            }
        }
        __syncthreads();

        // ---- stage 3: k3 from s_b -> s_a (pad >= 3, full h) ----
        #pragma unroll
        for (int j = 0; j < SLOTS; ++j) {
            if (mpad[j] >= 3) {
                evalk4(s_b, uN[j], dN[j], lN[j], rN[j],
                       svx[j], svy[j], svz[j], bxv[j], byv[j], bzv[j],
                       cex, dzf, negInv, alpha, kx, ky, kz);
                ax[j] = fmaf(2.0f, kx, ax[j]);
                ay[j] = fmaf(2.0f, ky, ay[j]);
                az[j] = fmaf(2.0f, kz, az[j]);
                svx[j] = fmaf(H, kx, mx[j]);
                svy[j] = fmaf(H, ky, my[j]);
                svz[j] = fmaf(H, kz, mz[j]);
                s_a[tid + j * NTHR] = make_float4(svx[j], svy[j], svz[j], 0.0f);
            }
        }
        __syncthreads();

        // ---- stage 4: k4 from s_a, combine, write global (owned only) ----
        #pragma unroll
        for (int j = 0; j < SLOTS; ++j) {
            if (mpad[j] >= HALO) {
                evalk4(s_a, uN[j], dN[j], lN[j], rN[j],
                       svx[j], svy[j], svz[j], bxv[j], byv[j], bzv[j],
                       cex, dzf, negInv, alpha, kx, ky, kz);
                float nx = fmaf(H6, ax[j] + kx, mx[j]);
                float ny = fmaf(H6, ay[j] + ky, my[j]);
                float nz = fmaf(H6, az[j] + kz, mz[j]);
                float4 nv = make_float4(nx, ny, nz, 0.0f);
                __stcg(&g_m[rp ^ 1][gld[j]], nv);   // owned: clamp == identity
                if (t == RELAX - 1) {               // m_relaxed snapshot (t=99)
                    __stcg(&g_mrel[gld[j]], nv);
                    if (pid[j] >= 0) pz0[j] = nz;
                }
                if (driven && pid[j] >= 0) {
                    float v = fb ? (nz - pz0[j]) * Msat : nz;
                    out[(t - RELAX) * NPROBE + pid[j]] = v;
                }
            }
        }

        // ---- publish step t complete (release; cumulative over barrier) ----
        __syncthreads();
        if (tid == 0) {
            unsigned nf = (unsigned)(t + 1);
            asm volatile("st.release.gpu.b32 [%0], %1;"
                         :: "l"(&g_flags[bid]), "r"(nf) : "memory");
        }
    }
}

// ---------------------------------------------------------------------------
extern "C" void kernel_launch(void* const* d_in, const int* in_sizes, int n_in,
                              void* d_out, int out_size) {
    (void)in_sizes; (void)out_size;
    const float* sig    = (const float*)d_in[0];
    const float* Bext   = (const float*)d_in[1];
    const float* Msat_p = (const float*)d_in[2];
    const int*   srcp   = (const int*)d_in[3];
    const int*   probep = (const int*)d_in[4];
    const int*   fbp;
    if (n_in > 5) {
        fbp = (const int*)d_in[5];
    } else {
        void* p = nullptr;
        cudaGetSymbolAddress(&p, g_zero_int);
        fbp = (const int*)p;
    }
    float* out = (float*)d_out;

    init_flags_kernel<<<1, NBLK>>>();
    mm_solver_kernel<<<NBLK, NTHR>>>(sig, Bext, Msat_p, srcp, probep, fbp, out);
}